// round 7
// baseline (speedup 1.0000x reference)
#include <cuda_runtime.h>
#include <cstdint>

// ---------------- problem dims ----------------
static constexpr int BATCH = 16;
static constexpr int HWD   = 64;
static constexpr int CH    = 256;           // Cin = Cout
static constexpr int KCH   = 32;            // K per ci-chunk
static constexpr int NCI   = CH / KCH;      // 8 ci-iterations
static constexpr int XP    = 66;            // padded spatial dim (1-halo)

// band: 4 rows x 66 cols x 32 ch, per-pixel stride 36 floats (conflict-free)
static constexpr int PIX_STRIDE = 36;
static constexpr int BAND_FLOATS = 4 * XP * PIX_STRIDE;    // 9504
static constexpr int SMEM_BYTES  = 2 * BAND_FLOATS * 4;    // 76032 -> 2 CTAs/SM

// ---------------- device scratch ----------------
__device__ float g_K2[CH * CH];
__device__ float g_d[BATCH * CH];
__device__ float g_B[72 * CH * KCH];                   // [chunk=tap*8+cis][co][kperm]
__device__ float g_xs[BATCH * XP * XP * CH];           // padded, modulated, permuted tf32

// ---------------- helpers ----------------
__device__ __forceinline__ float to_tf32(float v) {
    uint32_t u;
    asm("cvt.rna.tf32.f32 %0, %1;" : "=r"(u) : "f"(v));
    return __uint_as_float(u);
}
__device__ __forceinline__ uint32_t smem_u32(const void* p) {
    uint32_t a;
    asm("{ .reg .u64 t; cvta.to.shared.u64 t, %1; cvt.u32.u64 %0, t; }" : "=r"(a) : "l"(p));
    return a;
}
__device__ __forceinline__ void cp16(uint32_t dst_smem, const void* src) {
    asm volatile("cp.async.cg.shared.global [%0], [%1], 16;" :: "r"(dst_smem), "l"(src));
}
__device__ __forceinline__ void cp_commit() {
    asm volatile("cp.async.commit_group;" ::: "memory");
}
__device__ __forceinline__ void cp_wait0() {
    asm volatile("cp.async.wait_group 0;" ::: "memory");
}
__device__ __forceinline__ void mma_tf32(float* c, const uint32_t* a, const uint32_t* b) {
    asm volatile(
        "mma.sync.aligned.m16n8k8.row.col.f32.tf32.tf32.f32 "
        "{%0,%1,%2,%3}, {%4,%5,%6,%7}, {%8,%9}, {%0,%1,%2,%3};"
        : "+f"(c[0]), "+f"(c[1]), "+f"(c[2]), "+f"(c[3])
        : "r"(a[0]), "r"(a[1]), "r"(a[2]), "r"(a[3]), "r"(b[0]), "r"(b[1]));
}

// ---------------- prep kernels ----------------
__global__ void k2_kernel(const float* __restrict__ kern) {
    int co = threadIdx.x, ci = blockIdx.x;
    float acc = 0.f;
#pragma unroll
    for (int tap = 0; tap < 9; tap++) {
        float v = kern[(tap * CH + ci) * CH + co];
        acc += v * v;
    }
    g_K2[ci * CH + co] = acc;
}

__global__ void d_kernel(const float* __restrict__ style) {
    __shared__ float s2[CH];
    int b = blockIdx.x, t = threadIdx.x;
    float s = style[b * CH + t] + 1.0f;
    s2[t] = s * s;
    __syncthreads();
    float acc = 0.f;
#pragma unroll 8
    for (int ci = 0; ci < CH; ci++) acc += s2[ci] * g_K2[ci * CH + t];
    g_d[b * CH + t] = rsqrtf(acc + 1e-8f);
}

// pack kernel -> [chunk][co][kperm] tf32. perm p = 8*(k&3)+(k>>2) within 32.
__global__ void bprep_kernel(const float* __restrict__ kern) {
    int e = blockIdx.x * 256 + threadIdx.x;   // 589824
    int co = e & 255;
    int k  = e >> 8;                          // tap*256 + ci
    int chunk = k >> 5, kk = k & 31;
    int p = 8 * (kk & 3) + (kk >> 2);
    g_B[(size_t)chunk * (CH * KCH) + co * KCH + p] = to_tf32(kern[k * CH + co]);
}

// xs[b][h+1][w+1][perm(ci)] = tf32(x[b][h][w][ci] * (style+1))
__global__ void xsprep_kernel(const float* __restrict__ x, const float* __restrict__ style) {
    int idx = blockIdx.x * 256 + threadIdx.x;   // 4,194,304
    int v   = idx & 63;                         // channel quad 0..63
    int pos = idx >> 6;
    int w = pos & 63, h = (pos >> 6) & 63, b = pos >> 12;
    const float4 xv = *(const float4*)(x + ((size_t)((b * 64 + h) * 64 + w)) * CH + v * 4);
    const float4 sv = *(const float4*)(style + b * CH + v * 4);
    float vals[4];
    vals[0] = to_tf32(xv.x * (sv.x + 1.f));
    vals[1] = to_tf32(xv.y * (sv.y + 1.f));
    vals[2] = to_tf32(xv.z * (sv.z + 1.f));
    vals[3] = to_tf32(xv.w * (sv.w + 1.f));
    float* out = g_xs + ((size_t)((b * XP + h + 1) * XP + (w + 1))) * CH + ((v * 4) & ~31);
#pragma unroll
    for (int i = 0; i < 4; i++) {
        int kk = (4 * v + i) & 31;
        out[8 * (kk & 3) + (kk >> 2)] = vals[i];
    }
}

// zero the 1-wide halo ring of g_xs
__global__ void halo_kernel() {
    int idx = blockIdx.x * 256 + threadIdx.x;
    int b = blockIdx.y;
    int q = idx & 63;           // float4 within 256 ch
    int i = idx >> 6;           // halo position 0..259
    if (i >= 260) return;
    int h, w;
    if (i < 66)       { h = 0;  w = i; }
    else if (i < 132) { h = 65; w = i - 66; }
    else { int j = i - 132; h = 1 + (j >> 1); w = (j & 1) ? 65 : 0; }
    *(float4*)(g_xs + ((size_t)((b * XP + h) * XP + w)) * CH + q * 4) =
        make_float4(0.f, 0.f, 0.f, 0.f);
}

// ---------------- main kernel ----------------
// Grid: 1024 CTAs = 16 b x 32 mtiles x 2 ntiles. CTA: M=128 x N=128, K=2304.
// 128 threads = 4 warps, each warp: full M=128 x private N=32.
// ci-outer (8 iters, banded A in smem) / tap-inner (9 taps, B in registers from L2).
__global__ void __launch_bounds__(128, 2) conv_kernel(float* __restrict__ y) {
    extern __shared__ float sm[];
    const uint32_t sm_u32 = smem_u32(sm);

    const int tid  = threadIdx.x;
    const int lane = tid & 31;
    const int wid  = tid >> 5;
    const int gi   = lane >> 2;
    const int ti   = lane & 3;
    const int b    = blockIdx.x >> 6;
    const int mt   = (blockIdx.x >> 1) & 31;
    const int nt   = blockIdx.x & 1;
    const int h0   = mt * 2;
    const int cw   = nt * 128 + wid * 32;     // this warp's co base (global 0..255)

    // demod factors for this thread's 8 output columns
    float dv0[4], dv1[4];
#pragma unroll
    for (int ni = 0; ni < 4; ni++) {
        int c = cw + ni * 8 + 2 * ti;
        dv0[ni] = g_d[b * CH + c];
        dv1[ni] = g_d[b * CH + c + 1];
    }

    const float* xsb = g_xs + (size_t)b * XP * XP * CH;

    // B fragment global offsets (floats) within a chunk tile
    int bcol[4];
#pragma unroll
    for (int ni = 0; ni < 4; ni++) bcol[ni] = (cw + ni * 8 + gi) * KCH + 8 * ti;

// stage band for ci-chunk (cis) into buffer s: 2112 float4, 128 threads
#define STAGE(cis, s)                                                              \
    {                                                                              \
        const int ci0 = (cis) * KCH;                                               \
        const uint32_t dstb = sm_u32 + (uint32_t)(s) * (BAND_FLOATS * 4);          \
        _Pragma("unroll")                                                          \
        for (int j = 0; j < 17; j++) {                                             \
            int idx = j * 128 + tid;                                               \
            if (idx < 4 * XP * 8) {                                                \
                int pix = idx >> 3, seg = idx & 7;                                 \
                int hp = pix / XP, wp = pix - hp * XP;                             \
                cp16(dstb + (uint32_t)((pix * PIX_STRIDE + seg * 4) * 4),          \
                     xsb + ((size_t)((h0 + hp) * XP + wp)) * CH + ci0 + seg * 4);  \
            }                                                                      \
        }                                                                          \
        cp_commit();                                                               \
    }

#define LOADB(arr, chunk)                                                          \
    {                                                                              \
        const float* p = g_B + (size_t)(chunk) * (CH * KCH);                       \
        _Pragma("unroll")                                                          \
        for (int ni = 0; ni < 4; ni++) {                                           \
            arr[2 * ni]     = *(const float4*)(p + bcol[ni]);                      \
            arr[2 * ni + 1] = *(const float4*)(p + bcol[ni] + 4);                  \
        }                                                                          \
    }

// one tap: prefetch next B into BN, then 128 mma consuming BC + band A
#define TAP_BODY(BC, BN, tap)                                                      \
    {                                                                              \
        const int ntap = ((tap) == 8) ? 0 : ((tap) + 1);                           \
        const int ncis = ((tap) == 8) ? ((cis + 1) & 7) : cis;                     \
        LOADB(BN, ntap * 8 + ncis);                                                \
        const int kh = (tap) / 3, kw = (tap) % 3;                                  \
        const float* abase = band + (gi + kw) * PIX_STRIDE + 8 * ti               \
                             + kh * (XP * PIX_STRIDE);                             \
        _Pragma("unroll")                                                          \
        for (int half = 0; half < 2; half++) {                                     \
            _Pragma("unroll")                                                      \
            for (int mi = 0; mi < 8; mi++) {                                       \
                const float* ap = abase                                            \
                    + ((mi >> 2) * XP + (mi & 3) * 16) * PIX_STRIDE + 4 * half;    \
                float4 alo = *(const float4*)(ap);                                 \
                float4 ahi = *(const float4*)(ap + 8 * PIX_STRIDE);                \
                _Pragma("unroll")                                                  \
                for (int kf2 = 0; kf2 < 2; kf2++) {                                \
                    uint32_t af[4];                                                \
                    af[0] = __float_as_uint(kf2 ? alo.z : alo.x);                  \
                    af[1] = __float_as_uint(kf2 ? ahi.z : ahi.x);                  \
                    af[2] = __float_as_uint(kf2 ? alo.w : alo.y);                  \
                    af[3] = __float_as_uint(kf2 ? ahi.w : ahi.y);                  \
                    _Pragma("unroll")                                              \
                    for (int ni = 0; ni < 4; ni++) {                               \
                        float4 q = BC[2 * ni + half];                              \
                        uint32_t bf[2];                                            \
                        bf[0] = __float_as_uint(kf2 ? q.z : q.x);                  \
                        bf[1] = __float_as_uint(kf2 ? q.w : q.y);                  \
                        mma_tf32(acc[mi][ni], af, bf);                             \
                    }                                                              \
                }                                                                  \
            }                                                                      \
        }                                                                          \
    }

    float acc[8][4][4];
#pragma unroll
    for (int mi = 0; mi < 8; mi++)
#pragma unroll
        for (int ni = 0; ni < 4; ni++)
#pragma unroll
            for (int c = 0; c < 4; c++) acc[mi][ni][c] = 0.f;

    float4 bA[8], bB[8];

    STAGE(0, 0);
    LOADB(bA, 0);                 // tap 0, cis 0 -> chunk 0

    for (int cis = 0; cis < NCI; cis++) {
        const int s = cis & 1;
        cp_wait0();
        __syncthreads();
        if (cis + 1 < NCI) STAGE(cis + 1, s ^ 1);
        const float* band = sm + s * BAND_FLOATS;

        TAP_BODY(bA, bB, 0)
        TAP_BODY(bB, bA, 1)
        TAP_BODY(bA, bB, 2)
        TAP_BODY(bB, bA, 3)
        TAP_BODY(bA, bB, 4)
        TAP_BODY(bB, bA, 5)
        TAP_BODY(bA, bB, 6)
        TAP_BODY(bB, bA, 7)
        TAP_BODY(bA, bB, 8)       // prefetches next-iter tap0 into bB
#pragma unroll
        for (int j = 0; j < 8; j++) bA[j] = bB[j];   // restore parity
    }

    // ---- epilogue: demodulate + store NHWC ----
#pragma unroll
    for (int mi = 0; mi < 8; mi++) {
        const int hrow = h0 + (mi >> 2);
        const int w1 = (mi & 3) * 16 + gi;
        float* yr = y + (((size_t)b * HWD + hrow) * HWD + w1) * CH + cw;
#pragma unroll
        for (int ni = 0; ni < 4; ni++) {
            const int col = ni * 8 + 2 * ti;
            float2 o1, o2;
            o1.x = acc[mi][ni][0] * dv0[ni]; o1.y = acc[mi][ni][1] * dv1[ni];
            o2.x = acc[mi][ni][2] * dv0[ni]; o2.y = acc[mi][ni][3] * dv1[ni];
            *(float2*)(yr + col)            = o1;
            *(float2*)(yr + 8 * CH + col)   = o2;     // row m+8 = w1+8 same h
        }
    }
#undef STAGE
#undef LOADB
#undef TAP_BODY
}

// ---------------- launch ----------------
extern "C" void kernel_launch(void* const* d_in, const int* in_sizes, int n_in,
                              void* d_out, int out_size) {
    const float* x     = (const float*)d_in[0];   // [16,64,64,256]
    const float* style = (const float*)d_in[1];   // [16,256]
    const float* kern  = (const float*)d_in[2];   // [3,3,256,256]
    float* y = (float*)d_out;                     // [16,64,64,256]

    static bool attr_set = false;
    if (!attr_set) {
        cudaFuncSetAttribute(conv_kernel, cudaFuncAttributeMaxDynamicSharedMemorySize, SMEM_BYTES);
        attr_set = true;
    }

    k2_kernel<<<CH, CH>>>(kern);
    d_kernel<<<BATCH, CH>>>(style);
    bprep_kernel<<<9 * CH, 256>>>(kern);
    xsprep_kernel<<<16384, 256>>>(x, style);
    {
        dim3 g(65, 16);
        halo_kernel<<<g, 256>>>();
    }
    conv_kernel<<<BATCH * 32 * 2, 128, SMEM_BYTES>>>(y);
}

// round 9
// speedup vs baseline: 1.4416x; 1.4416x over previous
#include <cuda_runtime.h>
#include <cstdint>

// ---------------- problem dims ----------------
static constexpr int BATCH = 16;
static constexpr int HWD   = 64;
static constexpr int CH    = 256;           // Cin = Cout
static constexpr int KTOT  = 9 * CH;        // 2304
static constexpr int KCH   = 32;            // K per chunk
static constexpr int NCHUNK = KTOT / KCH;   // 72
static constexpr int AS    = 36;            // smem row stride (floats) -> conflict-free

static constexpr int CTA_N = 128;

// ---------------- device scratch ----------------
__device__ float g_K2[CH * CH];
__device__ float g_d[BATCH * CH];
__device__ float g_B[NCHUNK * CH * KCH];    // [chunk][co][kperm] tf32-rounded

// smem layout (floats): s[256] | d[256] | A 2x(128*36) | B 2x(128*36)
static constexpr int SM_S = 0;
static constexpr int SM_D = 256;
static constexpr int SM_A = 512;
static constexpr int A_BUF = 128 * AS;      // 4608 floats
static constexpr int SM_B = SM_A + 2 * A_BUF;
static constexpr int B_BUF = 128 * AS;      // 4608 floats
static constexpr int SMEM_FLOATS = SM_B + 2 * B_BUF;   // 18944
static constexpr int SMEM_BYTES  = SMEM_FLOATS * 4;    // 75776 -> 2 CTAs/SM

// ---------------- helpers ----------------
__device__ __forceinline__ float to_tf32(float v) {
    uint32_t u;
    asm("cvt.rna.tf32.f32 %0, %1;" : "=r"(u) : "f"(v));
    return __uint_as_float(u);
}
__device__ __forceinline__ uint32_t smem_u32(const void* p) {
    uint32_t a;
    asm("{ .reg .u64 t; cvta.to.shared.u64 t, %1; cvt.u32.u64 %0, t; }" : "=r"(a) : "l"(p));
    return a;
}
__device__ __forceinline__ void cp16(uint32_t dst_smem, const void* src) {
    asm volatile("cp.async.cg.shared.global [%0], [%1], 16;" :: "r"(dst_smem), "l"(src));
}
__device__ __forceinline__ void cp_commit() {
    asm volatile("cp.async.commit_group;" ::: "memory");
}
__device__ __forceinline__ void cp_wait0() {
    asm volatile("cp.async.wait_group 0;" ::: "memory");
}
__device__ __forceinline__ void mma_tf32(float* c, const uint32_t* a, const uint32_t* b) {
    asm volatile(
        "mma.sync.aligned.m16n8k8.row.col.f32.tf32.tf32.f32 "
        "{%0,%1,%2,%3}, {%4,%5,%6,%7}, {%8,%9}, {%0,%1,%2,%3};"
        : "+f"(c[0]), "+f"(c[1]), "+f"(c[2]), "+f"(c[3])
        : "r"(a[0]), "r"(a[1]), "r"(a[2]), "r"(a[3]), "r"(b[0]), "r"(b[1]));
}

// ---------------- prep kernels ----------------
__global__ void k2_kernel(const float* __restrict__ kern) {
    int co = threadIdx.x, ci = blockIdx.x;
    float acc = 0.f;
#pragma unroll
    for (int tap = 0; tap < 9; tap++) {
        float v = kern[(tap * CH + ci) * CH + co];
        acc += v * v;
    }
    g_K2[ci * CH + co] = acc;
}

__global__ void d_kernel(const float* __restrict__ style) {
    __shared__ float s2[CH];
    int b = blockIdx.x, t = threadIdx.x;
    float s = style[b * CH + t] + 1.0f;
    s2[t] = s * s;
    __syncthreads();
    float acc = 0.f;
#pragma unroll 8
    for (int ci = 0; ci < CH; ci++) acc += s2[ci] * g_K2[ci * CH + t];
    g_d[b * CH + t] = rsqrtf(acc + 1e-8f);
}

// pack kernel -> [chunk][co][kperm] tf32. perm p = 8*(k&3)+(k>>2) within 32.
__global__ void bprep_kernel(const float* __restrict__ kern) {
    int e = blockIdx.x * 256 + threadIdx.x;   // 589824
    int co = e & 255;
    int k  = e >> 8;                          // tap*256 + ci
    int chunk = k >> 5, kk = k & 31;
    int p = 8 * (kk & 3) + (kk >> 2);
    g_B[(size_t)chunk * (CH * KCH) + co * KCH + p] = to_tf32(kern[k * CH + co]);
}

// ---------------- main kernel ----------------
// Grid: 1024 CTAs = 16 b x 32 mtiles x 2 ntiles. CTA: M=128 x N=128, K=2304.
// 128 threads = 4 warps (2 M x 2 N), warp tile 64 x 64. 2 CTAs/SM.
// R4 skeleton; A's STS moved a full chunk ahead of its consuming barrier.
__global__ void __launch_bounds__(128, 2) conv_kernel(
    const float* __restrict__ x, const float* __restrict__ style, float* __restrict__ y) {
    extern __shared__ float sm[];
    float* s_s = sm + SM_S;
    float* s_d = sm + SM_D;
    float* sA  = sm + SM_A;
    float* sB  = sm + SM_B;
    const uint32_t sB_u32 = smem_u32(sB);

    const int tid  = threadIdx.x;
    const int lane = tid & 31;
    const int wid  = tid >> 5;
    const int b    = blockIdx.x >> 6;
    const int mt   = (blockIdx.x >> 1) & 31;
    const int nt   = blockIdx.x & 1;
    const int h0   = mt * 2;
    const int co0  = nt * CTA_N;

    for (int i = tid; i < CH; i += 128) s_s[i] = style[b * CH + i] + 1.0f;
    if (tid < CTA_N) s_d[tid] = g_d[b * CH + co0 + tid];
    __syncthreads();

    const float* xb = x + (size_t)b * HWD * HWD * CH;

    // A staging regs: 128 rows x 32 floats = 1024 float4, 8 per thread
    float4 ar[8];
    int a_ci0 = 0;
    const int r_base = tid >> 3;          // row for j: r_base + j*16
    const int v_     = tid & 7;

#define LOAD_A(chunk)                                                              \
    {                                                                              \
        int tap = (chunk) >> 3, sub = (chunk) & 7;                                 \
        int kh = tap / 3 - 1, kw = tap % 3 - 1;                                    \
        a_ci0 = sub * KCH;                                                         \
        _Pragma("unroll")                                                          \
        for (int j = 0; j < 8; j++) {                                              \
            int r = r_base + j * 16;                                               \
            int hi = h0 + (r >> 6) + kh, wi = (r & 63) + kw;                       \
            ar[j] = make_float4(0.f, 0.f, 0.f, 0.f);                               \
            if ((unsigned)hi < (unsigned)HWD && (unsigned)wi < (unsigned)HWD)      \
                ar[j] = *(const float4*)(xb + ((size_t)(hi * HWD + wi)) * CH + a_ci0 + v_ * 4); \
        }                                                                          \
    }

#define STORE_A(sbuf)                                                              \
    {                                                                              \
        float* abuf = sA + (sbuf) * A_BUF;                                         \
        float4 sv = *(const float4*)(s_s + a_ci0 + v_ * 4);                        \
        _Pragma("unroll")                                                          \
        for (int j = 0; j < 8; j++) {                                              \
            float4 o;                                                              \
            o.x = to_tf32(ar[j].x * sv.x); o.y = to_tf32(ar[j].y * sv.y);          \
            o.z = to_tf32(ar[j].z * sv.z); o.w = to_tf32(ar[j].w * sv.w);          \
            *(float4*)(abuf + (r_base + j * 16) * AS + v_ * 4) = o;                \
        }                                                                          \
    }

#define LOAD_B(chunk, sbuf)                                                        \
    {                                                                              \
        const float* gb = g_B + (size_t)(chunk) * (CH * KCH) + (size_t)co0 * KCH;  \
        uint32_t base = sB_u32 + (uint32_t)(sbuf) * (B_BUF * 4);                   \
        _Pragma("unroll")                                                          \
        for (int j = 0; j < 8; j++) {                                              \
            int u = j * 128 + tid;                                                 \
            int row = u >> 3, seg = u & 7;                                         \
            cp16(base + (uint32_t)(row * (AS * 4) + seg * 16), gb + u * 4);        \
        }                                                                          \
        cp_commit();                                                               \
    }

    // warp tiling: 2 wm x 2 wn, warp tile 64 x 64
    const int wm = wid & 1, wn = wid >> 1;
    const int m0 = wm * 64, n0 = wn * 64;
    const int gi = lane >> 2, ti = lane & 3;

    float acc[4][8][4];
#pragma unroll
    for (int mi = 0; mi < 4; mi++)
#pragma unroll
        for (int ni = 0; ni < 8; ni++)
#pragma unroll
            for (int c = 0; c < 4; c++) acc[mi][ni][c] = 0.f;

// one half = 8 B LDS.128 + 2 kf x 4 mi x (4 A LDS.32 + 8 HMMA)
#define MMA_HALF(half)                                                             \
    {                                                                              \
        float4 bq[8];                                                              \
        _Pragma("unroll")                                                          \
        for (int ni = 0; ni < 8; ni++)                                             \
            bq[ni] = *(const float4*)(Bw + ni * 8 * AS + (half) * 4);              \
        _Pragma("unroll")                                                          \
        for (int kf2 = 0; kf2 < 2; kf2++) {                                        \
            const int k0 = ((half) * 2 + kf2) * 8;                                 \
            _Pragma("unroll")                                                      \
            for (int mi = 0; mi < 4; mi++) {                                       \
                const float* ap = Aw + mi * (16 * AS) + k0;                        \
                uint32_t af[4];                                                    \
                af[0] = __float_as_uint(ap[0]);                                    \
                af[1] = __float_as_uint(ap[8 * AS]);                               \
                af[2] = __float_as_uint(ap[4]);                                    \
                af[3] = __float_as_uint(ap[8 * AS + 4]);                           \
                _Pragma("unroll")                                                  \
                for (int ni = 0; ni < 8; ni++) {                                   \
                    uint32_t bf[2];                                                \
                    bf[0] = __float_as_uint(kf2 ? bq[ni].z : bq[ni].x);            \
                    bf[1] = __float_as_uint(kf2 ? bq[ni].w : bq[ni].y);            \
                    mma_tf32(acc[mi][ni], af, bf);                                 \
                }                                                                  \
            }                                                                      \
        }                                                                          \
    }

    // prologue: A(0) staged into buf0; A(1) in regs; B(0) in flight
    LOAD_A(0);
    STORE_A(0);
    LOAD_A(1);
    LOAD_B(0, 0);

    for (int i = 0; i < NCHUNK; i++) {
        const int s = i & 1;
        cp_wait0();
        __syncthreads();                 // buf s: A(i) (stored a chunk ago), B(i) (cp'd a chunk ago)
        if (i + 1 < NCHUNK) LOAD_B(i + 1, s ^ 1);

        const float* Aw = sA + s * A_BUF + (m0 + gi) * AS + ti;
        const float* Bw = sB + s * B_BUF + (n0 + gi) * AS + 8 * ti;

        MMA_HALF(0)
        if (i + 1 < NCHUNK) STORE_A(s ^ 1);   // A(i+1) regs -> buf s^1 (WAR-safe: all reads of s^1 ended at this iter's barrier)
        if (i + 2 < NCHUNK) LOAD_A(i + 2);    // refill regs for next iter's store
        MMA_HALF(1)
    }

    // ---- epilogue: demodulate + store NHWC ----
#pragma unroll
    for (int mi = 0; mi < 4; mi++) {
        const int ma = m0 + mi * 16 + gi;
        const int mb = ma + 8;
        float* ya  = y + (((size_t)b * HWD + (h0 + (ma >> 6))) * HWD + (ma & 63)) * CH + co0;
        float* yb2 = y + (((size_t)b * HWD + (h0 + (mb >> 6))) * HWD + (mb & 63)) * CH + co0;
#pragma unroll
        for (int ni = 0; ni < 8; ni++) {
            const int col = n0 + ni * 8 + 2 * ti;   // local co
            const float d0 = s_d[col], d1 = s_d[col + 1];
            float2 oa, ob;
            oa.x = acc[mi][ni][0] * d0; oa.y = acc[mi][ni][1] * d1;
            ob.x = acc[mi][ni][2] * d0; ob.y = acc[mi][ni][3] * d1;
            *(float2*)(ya + col)  = oa;
            *(float2*)(yb2 + col) = ob;
        }
    }
#undef LOAD_A
#undef STORE_A
#undef LOAD_B
#undef MMA_HALF
}

// ---------------- launch ----------------
extern "C" void kernel_launch(void* const* d_in, const int* in_sizes, int n_in,
                              void* d_out, int out_size) {
    const float* x     = (const float*)d_in[0];   // [16,64,64,256]
    const float* style = (const float*)d_in[1];   // [16,256]
    const float* kern  = (const float*)d_in[2];   // [3,3,256,256]
    float* y = (float*)d_out;                     // [16,64,64,256]

    static bool attr_set = false;
    if (!attr_set) {
        cudaFuncSetAttribute(conv_kernel, cudaFuncAttributeMaxDynamicSharedMemorySize, SMEM_BYTES);
        attr_set = true;
    }

    k2_kernel<<<CH, CH>>>(kern);
    d_kernel<<<BATCH, CH>>>(style);
    bprep_kernel<<<KTOT, 256>>>(kern);
    conv_kernel<<<BATCH * 32 * 2, 128, SMEM_BYTES>>>(x, style, y);
}